// round 12
// baseline (speedup 1.0000x reference)
#include <cuda_runtime.h>
#include <cstdint>

#define NC 32
#define NU 5
#define NV 5
#define NH 64
#define NW 64

#define TILE_H 8
#define TILE_W 32
#define CHSTRIDE (NU * NV * NH * NW)   // 102400

typedef unsigned long long u64;

// per-warp x buffers (floats), per stage:
//  uvx: 9 planes x 10 rows x 32 cols (no w halo)  = 2880  @ 0
//  uvy: 9 planes x  8 rows x 40 cols              = 2880  @ 2880
//  uxy: 3 planes x 10 rows x 40 cols              = 1200  @ 5760
//  vxy: 3 planes x 10 rows x 40 cols              = 1200  @ 6960
#define XTOT   8160
#define WPER   216
#define STAGEF (XTOT + 4 * WPER)        // 9024 floats
#define SMEM_FLOATS (2 * STAGEF)        // 18048
#define SMEM_BYTES  (SMEM_FLOATS * 4)   // 72192

// Reorganized weights: [c][branch][tap][o], tap = (ka*3+kb)*3+kg
__device__ __align__(128) float g_wr[NC * 864];
__device__ float g_bias[32];
__device__ float g_slope[4];

__global__ void prep_kernel(const float* __restrict__ w0, const float* __restrict__ w1,
                            const float* __restrict__ w2, const float* __restrict__ w3,
                            const float* __restrict__ b0, const float* __restrict__ b1,
                            const float* __restrict__ b2, const float* __restrict__ b3,
                            const float* __restrict__ a0, const float* __restrict__ a1,
                            const float* __restrict__ a2, const float* __restrict__ a3)
{
    int t = blockIdx.x * blockDim.x + threadIdx.x;
    if (t < NC * 864) {
        int o   = t & 7;
        int tap = (t >> 3) % 27;
        int br  = (t / 216) & 3;
        int c   = t / 864;
        const float* w = (br == 0) ? w0 : (br == 1) ? w1 : (br == 2) ? w2 : w3;
        g_wr[t] = w[(o * NC + c) * 27 + tap];
    }
    if (t < 32) {
        const float* b = (t < 8) ? b0 : (t < 16) ? b1 : (t < 24) ? b2 : b3;
        g_bias[t] = b[t & 7];
    }
    if (t < 4) {
        const float* a = (t == 0) ? a0 : (t == 1) ? a1 : (t == 2) ? a2 : a3;
        g_slope[t] = a[0];
    }
}

// ---------- helpers ----------
__device__ __forceinline__ uint32_t smem_u32(const void* p) {
    uint32_t a;
    asm("{ .reg .u64 t; cvta.to.shared.u64 t, %1; cvt.u32.u64 %0, t; }" : "=r"(a) : "l"(p));
    return a;
}
__device__ __forceinline__ void cp16(uint32_t dst, const void* src) {
    asm volatile("cp.async.cg.shared.global [%0], [%1], 16;" :: "r"(dst), "l"(src) : "memory");
}
__device__ __forceinline__ void cp_commit() {
    asm volatile("cp.async.commit_group;" ::: "memory");
}
__device__ __forceinline__ void cp_wait1() {
    asm volatile("cp.async.wait_group 1;" ::: "memory");
}
__device__ __forceinline__ void cp_wait0() {
    asm volatile("cp.async.wait_group 0;" ::: "memory");
}
__device__ __forceinline__ void fma2(u64& acc, u64 a, u64 b) {
    asm("fma.rn.f32x2 %0, %1, %2, %0;" : "+l"(acc) : "l"(a), "l"(b));
}
__device__ __forceinline__ u64 splat2(float v) {
    u64 r;
    asm("mov.b64 %0, {%1, %1};" : "=l"(r) : "f"(v));
    return r;
}
__device__ __forceinline__ float2 unpack2(u64 v) {
    float2 r;
    asm("mov.b64 {%0, %1}, %2;" : "=f"(r.x), "=f"(r.y) : "l"(v));
    return r;
}

// ===== per-warp compute: one branch, 8 h-points x 8 oc per thread =====
// acc[p][j]: h point p, oc pair (2j, 2j+1).

// uvx: 9 planes (stride 320), 10 rows (stride 32), col wl (no halo).
__device__ __forceinline__ void comp_uvx(const float* __restrict__ s_x,
                                         const float* __restrict__ s_w,
                                         int wl, u64 (&acc)[8][4])
{
    #pragma unroll
    for (int ab = 0; ab < 9; ab++) {
        const float* col = s_x + ab * 320 + wl;
        u64 xs[10];
        #pragma unroll
        for (int r = 0; r < 10; r++) xs[r] = splat2(col[r * 32]);
        #pragma unroll
        for (int kg = 0; kg < 3; kg++) {
            const float* wp = s_w + (ab * 3 + kg) * 8;
            ulonglong2 w01 = *(const ulonglong2*)wp;
            ulonglong2 w23 = *(const ulonglong2*)(wp + 4);
            #pragma unroll
            for (int p = 0; p < 8; p++) {
                u64 xx = xs[p + kg];
                fma2(acc[p][0], xx, w01.x);
                fma2(acc[p][1], xx, w01.y);
                fma2(acc[p][2], xx, w23.x);
                fma2(acc[p][3], xx, w23.y);
            }
        }
    }
}

// uvy: 9 planes (stride 320), 8 rows (stride 40); col wl+3+kg, row p.
__device__ __forceinline__ void comp_uvy(const float* __restrict__ s_x,
                                         const float* __restrict__ s_w,
                                         int wl, u64 (&acc)[8][4])
{
    #pragma unroll
    for (int ab = 0; ab < 9; ab++) {
        const float* plb = s_x + 2880 + ab * 320;
        #pragma unroll
        for (int kg = 0; kg < 3; kg++) {
            const float* col = plb + (wl + 3 + kg);
            const float* wp = s_w + (ab * 3 + kg) * 8;
            ulonglong2 w01 = *(const ulonglong2*)wp;
            ulonglong2 w23 = *(const ulonglong2*)(wp + 4);
            #pragma unroll
            for (int p = 0; p < 8; p++) {
                u64 xx = splat2(col[p * 40]);
                fma2(acc[p][0], xx, w01.x);
                fma2(acc[p][1], xx, w01.y);
                fma2(acc[p][2], xx, w23.x);
                fma2(acc[p][3], xx, w23.y);
            }
        }
    }
}

// uxy (base 5760) / vxy (base 6960): 3 planes (stride 400), 10 rows (stride 40);
// row p+kb, col wl+3+kg.
__device__ __forceinline__ void comp_hw(const float* __restrict__ s_x,
                                        const float* __restrict__ s_w,
                                        int wl, int xbase, u64 (&acc)[8][4])
{
    #pragma unroll
    for (int ka = 0; ka < 3; ka++) {
        const float* plb = s_x + xbase + ka * 400;
        #pragma unroll
        for (int kg = 0; kg < 3; kg++) {
            const float* col = plb + (wl + 3 + kg);
            u64 xs[10];
            #pragma unroll
            for (int r = 0; r < 10; r++) xs[r] = splat2(col[r * 40]);
            #pragma unroll
            for (int kb = 0; kb < 3; kb++) {
                const float* wp = s_w + ((ka * 3 + kb) * 3 + kg) * 8;
                ulonglong2 w01 = *(const ulonglong2*)wp;
                ulonglong2 w23 = *(const ulonglong2*)(wp + 4);
                #pragma unroll
                for (int p = 0; p < 8; p++) {
                    u64 xx = xs[p + kb];
                    fma2(acc[p][0], xx, w01.x);
                    fma2(acc[p][1], xx, w01.y);
                    fma2(acc[p][2], xx, w23.x);
                    fma2(acc[p][3], xx, w23.y);
                }
            }
        }
    }
}

// ===================== main kernel =====================
__global__ __launch_bounds__(128, 3)
void fe_kernel(const float* __restrict__ x, float* __restrict__ out)
{
    extern __shared__ __align__(16) float sm[];

    const int tid = threadIdx.x;
    const int br  = tid >> 5;        // warp = branch 0..3
    const int wl  = tid & 31;        // w lane

    const int tile = blockIdx.x;             // 0..15
    const int tw   = (tile & 1) * TILE_W;
    const int th   = (tile >> 1) * TILE_H;   // 0..56
    const int uv   = blockIdx.y;             // 0..24
    const int u    = uv / 5, v = uv % 5;
    const int b    = blockIdx.z;             // 0..7

    // one-time zero (halo + channel-invariant OOB chunks)
    float4* z = (float4*)sm;
    #pragma unroll
    for (int i = tid; i < SMEM_FLOATS / 4; i += 128)
        z[i] = make_float4(0.f, 0.f, 0.f, 0.f);
    __syncthreads();

    // per-branch buffer bases; chunk k lands at xbase + k*16 bytes
    const int xpre = (br == 0) ? 0 : (br == 1) ? 2880 : (br == 2) ? 5760 : 6960;
    const float* sx_p[2] = { sm, sm + STAGEF };              // compute uses branch offsets inside
    const float* sw_p[2] = { sm + XTOT + br * WPER, sm + STAGEF + XTOT + br * WPER };
    uint32_t xdst[2], wdst[2];
    xdst[0] = smem_u32(sm + xpre) + wl * 16;
    xdst[1] = smem_u32(sm + STAGEF + xpre) + wl * 16;
    wdst[0] = smem_u32(sw_p[0]) + wl * 16;
    wdst[1] = smem_u32(sw_p[1]) + wl * 16;

    // ---- channel-invariant per-lane src offsets (bytes within a channel) ----
    int srcoff[23];
    #pragma unroll
    for (int i = 0; i < 23; i++) srcoff[i] = -1;
    if (br == 0) {              // uvx: 720 chunks = 9pl x 10r x 8ch (32 cols)
        #pragma unroll
        for (int i = 0; i < 23; i++) {
            int k = wl + 32 * i;
            if (k < 720) {
                int row = k >> 3, ch = k & 7;
                int ab = row / 10, r = row - ab * 10;
                int pa = ab / 3, pb = ab - pa * 3;
                int gu = u + pa - 1, gv = v + pb - 1;
                int gh = th + r - 1, gw = tw + ch * 4;
                if ((unsigned)gu < 5u && (unsigned)gv < 5u && (unsigned)gh < 64u)
                    srcoff[i] = (((gu * 5 + gv) * 64 + gh) * 64 + gw) * 4;
            }
        }
    } else if (br == 1) {       // uvy: 720 chunks = 9pl x 8r x 10ch (40 cols)
        #pragma unroll
        for (int i = 0; i < 23; i++) {
            int k = wl + 32 * i;
            if (k < 720) {
                int row = k / 10, ch = k - row * 10;
                int ab = row >> 3, r = row & 7;
                int pa = ab / 3, pb = ab - pa * 3;
                int gu = u + pa - 1, gv = v + pb - 1;
                int gh = th + r, gw = tw - 4 + ch * 4;
                if ((unsigned)gu < 5u && (unsigned)gv < 5u && (unsigned)gw < 64u)
                    srcoff[i] = (((gu * 5 + gv) * 64 + gh) * 64 + gw) * 4;
            }
        }
    } else {                    // uxy / vxy: 300 chunks = 3pl x 10r x 10ch
        #pragma unroll
        for (int i = 0; i < 10; i++) {
            int k = wl + 32 * i;
            if (k < 300) {
                int row = k / 10, ch = k - row * 10;
                int pk = row / 10, r = row - pk * 10;
                int gu = (br == 2) ? (u + pk - 1) : u;
                int gv = (br == 2) ? v : (v + pk - 1);
                int gh = th + r - 1, gw = tw - 4 + ch * 4;
                if ((unsigned)gu < 5u && (unsigned)gv < 5u &&
                    (unsigned)gh < 64u && (unsigned)gw < 64u)
                    srcoff[i] = (((gu * 5 + gv) * 64 + gh) * 64 + gw) * 4;
            }
        }
    }

    const char* xb = (const char*)(x + (size_t)b * NC * CHSTRIDE);
    const char* wbch = (const char*)(g_wr + br * WPER);
    const bool w2nd = (wl < 22);   // 54 weight chunks per channel

    // ---- stage channel 0 into buffer 0 ----
    {
        #pragma unroll
        for (int i = 0; i < 23; i++)
            if (srcoff[i] >= 0) cp16(xdst[0] + i * 512, xb + srcoff[i]);
        cp16(wdst[0], wbch + wl * 16);
        if (w2nd) cp16(wdst[0] + 512, wbch + 512 + wl * 16);
    }
    cp_commit();

    u64 acc[8][4];
    #pragma unroll
    for (int p = 0; p < 8; p++)
        #pragma unroll
        for (int j = 0; j < 4; j++) acc[p][j] = 0ull;

    #pragma unroll 1
    for (int c = 0; c < NC; c++) {
        const int s = c & 1;
        if (c < NC - 1) {
            __syncwarp();   // lanes done with buffer s^1 before refill
            const char* xc = xb + (size_t)(c + 1) * (CHSTRIDE * 4);
            const char* wc = wbch + (size_t)(c + 1) * (864 * 4);
            #pragma unroll
            for (int i = 0; i < 23; i++)
                if (srcoff[i] >= 0) cp16(xdst[s ^ 1] + i * 512, xc + srcoff[i]);
            cp16(wdst[s ^ 1], wc + wl * 16);
            if (w2nd) cp16(wdst[s ^ 1] + 512, wc + 512 + wl * 16);
            cp_commit();
            cp_wait1();
        } else {
            cp_wait0();
        }
        __syncwarp();

        if (br == 0)      comp_uvx(sx_p[s], sw_p[s], wl, acc);
        else if (br == 1) comp_uvy(sx_p[s], sw_p[s], wl, acc);
        else if (br == 2) comp_hw(sx_p[s], sw_p[s], wl, 5760, acc);
        else              comp_hw(sx_p[s], sw_p[s], wl, 6960, acc);
    }

    // ---- epilogue: bias + PReLU + store (warp-private) ----
    const float slope = g_slope[br];
    const int ocb = br * 8;
    const size_t base0 = (size_t)b * 32 * CHSTRIDE + (size_t)ocb * CHSTRIDE +
                         (size_t)uv * (NH * NW) + (size_t)th * NW + (size_t)(tw + wl);
    #pragma unroll
    for (int j = 0; j < 4; j++) {
        const float b0 = g_bias[ocb + j * 2];
        const float b1 = g_bias[ocb + j * 2 + 1];
        const size_t cb0 = base0 + (size_t)(j * 2) * CHSTRIDE;
        const size_t cb1 = base0 + (size_t)(j * 2 + 1) * CHSTRIDE;
        #pragma unroll
        for (int p = 0; p < 8; p++) {
            float2 y = unpack2(acc[p][j]);
            float y0 = y.x + b0;
            float y1 = y.y + b1;
            y0 = (y0 >= 0.f) ? y0 : slope * y0;
            y1 = (y1 >= 0.f) ? y1 : slope * y1;
            out[cb0 + (size_t)p * NW] = y0;
            out[cb1 + (size_t)p * NW] = y1;
        }
    }
}

extern "C" void kernel_launch(void* const* d_in, const int* in_sizes, int n_in,
                              void* d_out, int out_size)
{
    const float* x = (const float*)d_in[0];

    prep_kernel<<<(NC * 864 + 255) / 256, 256>>>(
        (const float*)d_in[1], (const float*)d_in[4],
        (const float*)d_in[7], (const float*)d_in[10],
        (const float*)d_in[2], (const float*)d_in[5],
        (const float*)d_in[8], (const float*)d_in[11],
        (const float*)d_in[3], (const float*)d_in[6],
        (const float*)d_in[9], (const float*)d_in[12]);

    static bool attr_set = false;
    if (!attr_set) {
        cudaFuncSetAttribute(fe_kernel, cudaFuncAttributeMaxDynamicSharedMemorySize,
                             SMEM_BYTES);
        attr_set = true;
    }

    dim3 grid(16, 25, 8);   // (hw tiles: 2w x 8h, uv, batch)
    fe_kernel<<<grid, 128, SMEM_BYTES>>>(x, (float*)d_out);
}

// round 14
// speedup vs baseline: 1.0649x; 1.0649x over previous
#include <cuda_runtime.h>
#include <cstdint>

#define NC 32
#define NU 5
#define NV 5
#define NH 64
#define NW 64

#define TILE_H 8
#define TILE_W 32
#define CHSTRIDE (NU * NV * NH * NW)   // 102400
#define CHB      (CHSTRIDE * 4)        // bytes per channel

typedef unsigned long long u64;

// stage layout (floats):
//  union (uvx+uvy): 9 planes x 10 rows x 40 cols = 3600 @ 0   (plane 400, row 40)
//  uxy:             3 planes x 10 rows x 40 cols = 1200 @ 3600
//  vxy:             3 planes x 10 rows x 40 cols = 1200 @ 4800
//  w:               4 x 216                      =  864 @ 6000
#define UXY_F   3600
#define VXY_F   4800
#define WB_F    6000
#define STAGEF  6880                    // padded (6864 used)
#define STAGEB  (STAGEF * 4)            // 27520 bytes
#define SMEM_BYTES (2 * STAGEB)         // 55040

// Reorganized weights: [c][branch][tap][o], tap = (ka*3+kb)*3+kg
__device__ __align__(128) float g_wr[NC * 864];
__device__ float g_bias[32];
__device__ float g_slope[4];

__global__ void prep_kernel(const float* __restrict__ w0, const float* __restrict__ w1,
                            const float* __restrict__ w2, const float* __restrict__ w3,
                            const float* __restrict__ b0, const float* __restrict__ b1,
                            const float* __restrict__ b2, const float* __restrict__ b3,
                            const float* __restrict__ a0, const float* __restrict__ a1,
                            const float* __restrict__ a2, const float* __restrict__ a3)
{
    int t = blockIdx.x * blockDim.x + threadIdx.x;
    if (t < NC * 864) {
        int o   = t & 7;
        int tap = (t >> 3) % 27;
        int br  = (t / 216) & 3;
        int c   = t / 864;
        const float* w = (br == 0) ? w0 : (br == 1) ? w1 : (br == 2) ? w2 : w3;
        g_wr[t] = w[(o * NC + c) * 27 + tap];
    }
    if (t < 32) {
        const float* b = (t < 8) ? b0 : (t < 16) ? b1 : (t < 24) ? b2 : b3;
        g_bias[t] = b[t & 7];
    }
    if (t < 4) {
        const float* a = (t == 0) ? a0 : (t == 1) ? a1 : (t == 2) ? a2 : a3;
        g_slope[t] = a[0];
    }
}

// ---------- helpers ----------
__device__ __forceinline__ uint32_t smem_u32(const void* p) {
    uint32_t a;
    asm("{ .reg .u64 t; cvta.to.shared.u64 t, %1; cvt.u32.u64 %0, t; }" : "=r"(a) : "l"(p));
    return a;
}
__device__ __forceinline__ void cp16(uint32_t dst, const void* src) {
    asm volatile("cp.async.cg.shared.global [%0], [%1], 16;" :: "r"(dst), "l"(src) : "memory");
}
__device__ __forceinline__ void cp_commit() {
    asm volatile("cp.async.commit_group;" ::: "memory");
}
__device__ __forceinline__ void cp_wait1() {
    asm volatile("cp.async.wait_group 1;" ::: "memory");
}
__device__ __forceinline__ void cp_wait0() {
    asm volatile("cp.async.wait_group 0;" ::: "memory");
}
__device__ __forceinline__ void bar_sync(int id, int cnt) {
    asm volatile("bar.sync %0, %1;" :: "r"(id), "r"(cnt) : "memory");
}
__device__ __forceinline__ void fma2(u64& acc, u64 a, u64 b) {
    asm("fma.rn.f32x2 %0, %1, %2, %0;" : "+l"(acc) : "l"(a), "l"(b));
}
__device__ __forceinline__ u64 splat2(float v) {
    u64 r;
    asm("mov.b64 %0, {%1, %1};" : "=l"(r) : "f"(v));
    return r;
}
__device__ __forceinline__ float2 unpack2(u64 v) {
    float2 r;
    asm("mov.b64 {%0, %1}, %2;" : "=f"(r.x), "=f"(r.y) : "l"(v));
    return r;
}

// packed-offset staging: NE entries, 16-bit chunk indices (0xFFFF = skip)
template<int NE>
__device__ __forceinline__ void stage_x(const uint32_t* pk, uint32_t dst,
                                        const char* xc)
{
    #pragma unroll
    for (int i = 0; i < NE; i++) {
        uint32_t h16 = (pk[i >> 1] >> (16 * (i & 1))) & 0xFFFFu;
        if (h16 != 0xFFFFu) cp16(dst + i * 512, xc + (size_t)h16 * 16);
    }
}
__device__ __forceinline__ void stage_w(uint32_t dst, const char* wc, int wl)
{
    cp16(dst, wc + wl * 16);
    if (wl < 22) cp16(dst + 512, wc + 512 + wl * 16);
}

// ===== compute: 8 h-points x 8 oc per thread =====
// acc[p][j]: h point p, oc pair (2j, 2j+1).

// uvx from union buffer: plane 400, row 40, col wl+4; rows p+kg
__device__ __forceinline__ void comp_uvx(const float* __restrict__ sx,
                                         const float* __restrict__ sw,
                                         int wl, u64 (&acc)[8][4])
{
    #pragma unroll
    for (int ab = 0; ab < 9; ab++) {
        const float* col = sx + ab * 400 + (wl + 4);
        u64 xs[10];
        #pragma unroll
        for (int r = 0; r < 10; r++) xs[r] = splat2(col[r * 40]);
        #pragma unroll
        for (int kg = 0; kg < 3; kg++) {
            const float* wp = sw + (ab * 3 + kg) * 8;
            ulonglong2 w01 = *(const ulonglong2*)wp;
            ulonglong2 w23 = *(const ulonglong2*)(wp + 4);
            #pragma unroll
            for (int p = 0; p < 8; p++) {
                u64 xx = xs[p + kg];
                fma2(acc[p][0], xx, w01.x);
                fma2(acc[p][1], xx, w01.y);
                fma2(acc[p][2], xx, w23.x);
                fma2(acc[p][3], xx, w23.y);
            }
        }
    }
}

// uvy from union buffer: row p+1, col wl+3+kg
__device__ __forceinline__ void comp_uvy(const float* __restrict__ sx,
                                         const float* __restrict__ sw,
                                         int wl, u64 (&acc)[8][4])
{
    #pragma unroll
    for (int ab = 0; ab < 9; ab++) {
        const float* plb = sx + ab * 400;
        #pragma unroll
        for (int kg = 0; kg < 3; kg++) {
            const float* col = plb + (wl + 3 + kg);
            const float* wp = sw + (ab * 3 + kg) * 8;
            ulonglong2 w01 = *(const ulonglong2*)wp;
            ulonglong2 w23 = *(const ulonglong2*)(wp + 4);
            #pragma unroll
            for (int p = 0; p < 8; p++) {
                u64 xx = splat2(col[(p + 1) * 40]);
                fma2(acc[p][0], xx, w01.x);
                fma2(acc[p][1], xx, w01.y);
                fma2(acc[p][2], xx, w23.x);
                fma2(acc[p][3], xx, w23.y);
            }
        }
    }
}

// uxy / vxy from private 3-plane buffer: plane 400, row p+kb, col wl+3+kg
__device__ __forceinline__ void comp_hw(const float* __restrict__ sx,
                                        const float* __restrict__ sw,
                                        int wl, u64 (&acc)[8][4])
{
    #pragma unroll
    for (int ka = 0; ka < 3; ka++) {
        const float* plb = sx + ka * 400;
        #pragma unroll
        for (int kg = 0; kg < 3; kg++) {
            const float* col = plb + (wl + 3 + kg);
            u64 xs[10];
            #pragma unroll
            for (int r = 0; r < 10; r++) xs[r] = splat2(col[r * 40]);
            #pragma unroll
            for (int kb = 0; kb < 3; kb++) {
                const float* wp = sw + ((ka * 3 + kb) * 3 + kg) * 8;
                ulonglong2 w01 = *(const ulonglong2*)wp;
                ulonglong2 w23 = *(const ulonglong2*)(wp + 4);
                #pragma unroll
                for (int p = 0; p < 8; p++) {
                    u64 xx = xs[p + kb];
                    fma2(acc[p][0], xx, w01.x);
                    fma2(acc[p][1], xx, w01.y);
                    fma2(acc[p][2], xx, w23.x);
                    fma2(acc[p][3], xx, w23.y);
                }
            }
        }
    }
}

// ===================== main kernel =====================
__global__ __launch_bounds__(128, 4)
void fe_kernel(const float* __restrict__ x, float* __restrict__ out)
{
    extern __shared__ __align__(16) float sm[];
    const uint32_t sbase = smem_u32(sm);

    const int tid = threadIdx.x;
    const int br  = tid >> 5;        // warp = branch 0..3
    const int wl  = tid & 31;

    const int tile = blockIdx.x;             // 0..15
    const int tw   = (tile & 1) * TILE_W;
    const int th   = (tile >> 1) * TILE_H;   // 0..56
    const int uv   = blockIdx.y;             // 0..24
    const int u    = uv / 5, v = uv % 5;
    const int b    = blockIdx.z;             // 0..7

    // zero data region (halo + OOB chunks; channel-invariant)
    float4* z = (float4*)sm;
    #pragma unroll
    for (int i = tid; i < (2 * STAGEF) / 4; i += 128)
        z[i] = make_float4(0.f, 0.f, 0.f, 0.f);
    __syncthreads();

    // ---- packed channel-invariant per-lane chunk offsets ----
    uint32_t pk[8];
    #pragma unroll
    for (int i = 0; i < 8; i++) pk[i] = 0xFFFFFFFFu;

    int kbase;
    if (br < 2) {               // union: 900 chunks; warp0 k<448, warp1 448..899
        kbase = br ? 448 : 0;
        const int ne = br ? 15 : 14;
        for (int i = 0; i < ne; i++) {
            int k = kbase + wl + 32 * i;
            uint32_t val = 0xFFFFu;
            if (k < 900) {
                int row = k / 10, ch = k - row * 10;
                int ab = row / 10, r = row - ab * 10;
                int gu = u + ab / 3 - 1, gv = v + ab % 3 - 1;
                int gh = th + r - 1,     gw = tw - 4 + ch * 4;
                if ((unsigned)gu < 5u && (unsigned)gv < 5u &&
                    (unsigned)gh < 64u && (unsigned)gw < 64u)
                    val = (uint32_t)((((gu * 5 + gv) * 64 + gh) * 64 + gw) >> 2);
            }
            int sh = 16 * (i & 1);
            pk[i >> 1] = (pk[i >> 1] & ~(0xFFFFu << sh)) | (val << sh);
        }
    } else {                    // uxy/vxy: 300 chunks = 3pl x 10r x 10ch
        kbase = 0;
        for (int i = 0; i < 10; i++) {
            int k = wl + 32 * i;
            uint32_t val = 0xFFFFu;
            if (k < 300) {
                int row = k / 10, ch = k - row * 10;
                int pkn = row / 10, r = row - pkn * 10;
                int gu = (br == 2) ? (u + pkn - 1) : u;
                int gv = (br == 2) ? v : (v + pkn - 1);
                int gh = th + r - 1, gw = tw - 4 + ch * 4;
                if ((unsigned)gu < 5u && (unsigned)gv < 5u &&
                    (unsigned)gh < 64u && (unsigned)gw < 64u)
                    val = (uint32_t)((((gu * 5 + gv) * 64 + gh) * 64 + gw) >> 2);
            }
            int sh = 16 * (i & 1);
            pk[i >> 1] = (pk[i >> 1] & ~(0xFFFFu << sh)) | (val << sh);
        }
    }

    const int xoff_f = (br < 2) ? 0 : (br == 2 ? UXY_F : VXY_F);
    uint32_t dstx[2], dstw[2];
    dstx[0] = sbase + xoff_f * 4 + (kbase + wl) * 16;
    dstx[1] = dstx[0] + STAGEB;
    dstw[0] = sbase + (WB_F + br * 216) * 4 + wl * 16;
    dstw[1] = dstw[0] + STAGEB;
    const float* sx_p[2] = { sm + xoff_f,          sm + STAGEF + xoff_f };
    const float* sw_p[2] = { sm + WB_F + br * 216, sm + STAGEF + WB_F + br * 216 };

    const char* xb = (const char*)x + (size_t)b * NC * CHB;
    const char* wb = (const char*)(g_wr + br * 216);

    u64 acc[8][4];
    #pragma unroll
    for (int p = 0; p < 8; p++)
        #pragma unroll
        for (int j = 0; j < 4; j++) acc[p][j] = 0ull;

    if (br < 2) {
        // ===== uv warps: shared union buffer, named-barrier (id 1, 64 thr) =====
        stage_x<15>(pk, dstx[0], xb);
        stage_w(dstw[0], wb, wl);
        cp_commit();

        #pragma unroll 1
        for (int c = 0; c < NC; c++) {
            const int s = c & 1;
            if (c < NC - 1) {
                bar_sync(1, 64);   // peers done computing c-1 from buffer s^1
                stage_x<15>(pk, dstx[s ^ 1], xb + (size_t)(c + 1) * CHB);
                stage_w(dstw[s ^ 1], wb + (size_t)(c + 1) * 3456, wl);
                cp_commit();
                cp_wait1();        // own channel-c data complete
            } else {
                cp_wait0();
            }
            bar_sync(1, 64);       // peers' channel-c data complete + visible

            if (br == 0) comp_uvx(sx_p[s], sw_p[s], wl, acc);
            else         comp_uvy(sx_p[s], sw_p[s], wl, acc);
        }
    } else {
        // ===== hw warps: private buffers, wait_group pipeline (R11 style) =====
        stage_x<10>(pk, dstx[0], xb);
        stage_w(dstw[0], wb, wl);
        cp_commit();

        #pragma unroll 1
        for (int c = 0; c < NC; c++) {
            const int s = c & 1;
            if (c < NC - 1) {
                __syncwarp();
                stage_x<10>(pk, dstx[s ^ 1], xb + (size_t)(c + 1) * CHB);
                stage_w(dstw[s ^ 1], wb + (size_t)(c + 1) * 3456, wl);
                cp_commit();
                cp_wait1();
            } else {
                cp_wait0();
            }
            __syncwarp();
            comp_hw(sx_p[s], sw_p[s], wl, acc);
        }
    }

    // ---- epilogue: bias + PReLU + store ----
    const float slope = g_slope[br];
    const int ocb = br * 8;
    const size_t base0 = (size_t)b * 32 * CHSTRIDE + (size_t)ocb * CHSTRIDE +
                         (size_t)uv * (NH * NW) + (size_t)th * NW + (size_t)(tw + wl);
    #pragma unroll
    for (int j = 0; j < 4; j++) {
        const float b0 = g_bias[ocb + j * 2];
        const float b1 = g_bias[ocb + j * 2 + 1];
        const size_t cb0 = base0 + (size_t)(j * 2) * CHSTRIDE;
        const size_t cb1 = base0 + (size_t)(j * 2 + 1) * CHSTRIDE;
        #pragma unroll
        for (int p = 0; p < 8; p++) {
            float2 y = unpack2(acc[p][j]);
            float y0 = y.x + b0;
            float y1 = y.y + b1;
            y0 = (y0 >= 0.f) ? y0 : slope * y0;
            y1 = (y1 >= 0.f) ? y1 : slope * y1;
            out[cb0 + (size_t)p * NW] = y0;
            out[cb1 + (size_t)p * NW] = y1;
        }
    }
}

extern "C" void kernel_launch(void* const* d_in, const int* in_sizes, int n_in,
                              void* d_out, int out_size)
{
    const float* x = (const float*)d_in[0];

    prep_kernel<<<(NC * 864 + 255) / 256, 256>>>(
        (const float*)d_in[1], (const float*)d_in[4],
        (const float*)d_in[7], (const float*)d_in[10],
        (const float*)d_in[2], (const float*)d_in[5],
        (const float*)d_in[8], (const float*)d_in[11],
        (const float*)d_in[3], (const float*)d_in[6],
        (const float*)d_in[9], (const float*)d_in[12]);

    static bool attr_set = false;
    if (!attr_set) {
        cudaFuncSetAttribute(fe_kernel, cudaFuncAttributeMaxDynamicSharedMemorySize,
                             SMEM_BYTES);
        attr_set = true;
    }

    dim3 grid(16, 25, 8);   // (hw tiles: 2w x 8h, uv, batch)
    fe_kernel<<<grid, 128, SMEM_BYTES>>>(x, (float*)d_out);
}

// round 15
// speedup vs baseline: 1.3722x; 1.2886x over previous
#include <cuda_runtime.h>
#include <cstdint>

#define NC 32
#define NU 5
#define NV 5
#define NH 64
#define NW 64

#define TILE_H 4
#define TILE_W 32
#define CHSTRIDE (NU * NV * NH * NW)   // 102400
#define CHB      (CHSTRIDE * 4)

typedef unsigned long long u64;

// stage layout (floats):
//  union (uvx+uvy): 9 planes x 6 rows x 40 cols = 2160 @ 0   (plane 240, row 40)
//  uxy:             3 planes x 6 rows x 40 cols =  720 @ 2160
//  vxy:             3 planes x 6 rows x 40 cols =  720 @ 2880
//  w:               4 x 216                     =  864 @ 3600
#define UXY_F   2160
#define VXY_F   2880
#define WB_F    3600
#define STAGEF  4464
#define STAGEB  (STAGEF * 4)            // 17856 bytes
#define SMEM_FLOATS (2 * STAGEF)        // 8928 (35712 B)

// Reorganized weights: [c][branch][tap][o], tap = (ka*3+kb)*3+kg
__device__ __align__(128) float g_wr[NC * 864];
__device__ float g_bias[32];
__device__ float g_slope[4];

__global__ void prep_kernel(const float* __restrict__ w0, const float* __restrict__ w1,
                            const float* __restrict__ w2, const float* __restrict__ w3,
                            const float* __restrict__ b0, const float* __restrict__ b1,
                            const float* __restrict__ b2, const float* __restrict__ b3,
                            const float* __restrict__ a0, const float* __restrict__ a1,
                            const float* __restrict__ a2, const float* __restrict__ a3)
{
    int t = blockIdx.x * blockDim.x + threadIdx.x;
    if (t < NC * 864) {
        int o   = t & 7;
        int tap = (t >> 3) % 27;
        int br  = (t / 216) & 3;
        int c   = t / 864;
        const float* w = (br == 0) ? w0 : (br == 1) ? w1 : (br == 2) ? w2 : w3;
        g_wr[t] = w[(o * NC + c) * 27 + tap];
    }
    if (t < 32) {
        const float* b = (t < 8) ? b0 : (t < 16) ? b1 : (t < 24) ? b2 : b3;
        g_bias[t] = b[t & 7];
    }
    if (t < 4) {
        const float* a = (t == 0) ? a0 : (t == 1) ? a1 : (t == 2) ? a2 : a3;
        g_slope[t] = a[0];
    }
}

// ---------- helpers ----------
__device__ __forceinline__ uint32_t smem_u32(const void* p) {
    uint32_t a;
    asm("{ .reg .u64 t; cvta.to.shared.u64 t, %1; cvt.u32.u64 %0, t; }" : "=r"(a) : "l"(p));
    return a;
}
__device__ __forceinline__ void cp16(uint32_t dst, const void* src) {
    asm volatile("cp.async.cg.shared.global [%0], [%1], 16;" :: "r"(dst), "l"(src) : "memory");
}
__device__ __forceinline__ void cp_commit() {
    asm volatile("cp.async.commit_group;" ::: "memory");
}
__device__ __forceinline__ void cp_wait1() {
    asm volatile("cp.async.wait_group 1;" ::: "memory");
}
__device__ __forceinline__ void cp_wait0() {
    asm volatile("cp.async.wait_group 0;" ::: "memory");
}
__device__ __forceinline__ void bar_sync(int id, int cnt) {
    asm volatile("bar.sync %0, %1;" :: "r"(id), "r"(cnt) : "memory");
}
__device__ __forceinline__ void fma2(u64& acc, u64 a, u64 b) {
    asm("fma.rn.f32x2 %0, %1, %2, %0;" : "+l"(acc) : "l"(a), "l"(b));
}
__device__ __forceinline__ u64 splat2(float v) {
    u64 r;
    asm("mov.b64 %0, {%1, %1};" : "=l"(r) : "f"(v));
    return r;
}
__device__ __forceinline__ float2 unpack2(u64 v) {
    float2 r;
    asm("mov.b64 {%0, %1}, %2;" : "=f"(r.x), "=f"(r.y) : "l"(v));
    return r;
}

// packed-offset staging: NE entries, u16 chunk indices (0xFFFF = skip)
template<int NE>
__device__ __forceinline__ void stage_x(const uint32_t* pk, uint32_t dst,
                                        const char* xc)
{
    #pragma unroll
    for (int i = 0; i < NE; i++) {
        uint32_t h16 = (pk[i >> 1] >> (16 * (i & 1))) & 0xFFFFu;
        if (h16 != 0xFFFFu) cp16(dst + i * 512, xc + (size_t)h16 * 16);
    }
}
__device__ __forceinline__ void stage_w(uint32_t dst, const char* wc, int wl)
{
    cp16(dst, wc + wl * 16);
    if (wl < 22) cp16(dst + 512, wc + 512 + wl * 16);
}

// ===== compute: 4 h-points x 8 oc per thread =====
// acc[p][j]: h point p, oc pair (2j, 2j+1).

// uvx from union: plane 240, row 40, col wl+4; rows p+kg (0..5)
__device__ __forceinline__ void comp_uvx(const float* __restrict__ sx,
                                         const float* __restrict__ sw,
                                         int wl, u64 (&acc)[4][4])
{
    #pragma unroll
    for (int ab = 0; ab < 9; ab++) {
        const float* col = sx + ab * 240 + (wl + 4);
        u64 xs[6];
        #pragma unroll
        for (int r = 0; r < 6; r++) xs[r] = splat2(col[r * 40]);
        #pragma unroll
        for (int kg = 0; kg < 3; kg++) {
            const float* wp = sw + (ab * 3 + kg) * 8;
            ulonglong2 w01 = *(const ulonglong2*)wp;
            ulonglong2 w23 = *(const ulonglong2*)(wp + 4);
            #pragma unroll
            for (int p = 0; p < 4; p++) {
                u64 xx = xs[p + kg];
                fma2(acc[p][0], xx, w01.x);
                fma2(acc[p][1], xx, w01.y);
                fma2(acc[p][2], xx, w23.x);
                fma2(acc[p][3], xx, w23.y);
            }
        }
    }
}

// uvy from union: row p+1 (1..4), col wl+3+kg
__device__ __forceinline__ void comp_uvy(const float* __restrict__ sx,
                                         const float* __restrict__ sw,
                                         int wl, u64 (&acc)[4][4])
{
    #pragma unroll
    for (int ab = 0; ab < 9; ab++) {
        const float* plb = sx + ab * 240;
        #pragma unroll
        for (int kg = 0; kg < 3; kg++) {
            const float* col = plb + (wl + 3 + kg);
            const float* wp = sw + (ab * 3 + kg) * 8;
            ulonglong2 w01 = *(const ulonglong2*)wp;
            ulonglong2 w23 = *(const ulonglong2*)(wp + 4);
            #pragma unroll
            for (int p = 0; p < 4; p++) {
                u64 xx = splat2(col[(p + 1) * 40]);
                fma2(acc[p][0], xx, w01.x);
                fma2(acc[p][1], xx, w01.y);
                fma2(acc[p][2], xx, w23.x);
                fma2(acc[p][3], xx, w23.y);
            }
        }
    }
}

// uxy / vxy from private 3-plane buffer: plane 240, row p+kb, col wl+3+kg
__device__ __forceinline__ void comp_hw(const float* __restrict__ sx,
                                        const float* __restrict__ sw,
                                        int wl, u64 (&acc)[4][4])
{
    #pragma unroll
    for (int ka = 0; ka < 3; ka++) {
        const float* plb = sx + ka * 240;
        #pragma unroll
        for (int kg = 0; kg < 3; kg++) {
            const float* col = plb + (wl + 3 + kg);
            u64 xs[6];
            #pragma unroll
            for (int r = 0; r < 6; r++) xs[r] = splat2(col[r * 40]);
            #pragma unroll
            for (int kb = 0; kb < 3; kb++) {
                const float* wp = sw + ((ka * 3 + kb) * 3 + kg) * 8;
                ulonglong2 w01 = *(const ulonglong2*)wp;
                ulonglong2 w23 = *(const ulonglong2*)(wp + 4);
                #pragma unroll
                for (int p = 0; p < 4; p++) {
                    u64 xx = xs[p + kb];
                    fma2(acc[p][0], xx, w01.x);
                    fma2(acc[p][1], xx, w01.y);
                    fma2(acc[p][2], xx, w23.x);
                    fma2(acc[p][3], xx, w23.y);
                }
            }
        }
    }
}

// ===================== main kernel =====================
__global__ __launch_bounds__(128, 4)
void fe_kernel(const float* __restrict__ x, float* __restrict__ out)
{
    __shared__ __align__(16) float sm[SMEM_FLOATS];
    const uint32_t sbase = smem_u32(sm);

    const int tid = threadIdx.x;
    const int br  = tid >> 5;        // warp = branch 0..3
    const int wl  = tid & 31;

    const int tile = blockIdx.x;             // 0..31
    const int tw   = (tile & 1) * TILE_W;
    const int th   = (tile >> 1) * TILE_H;   // 0..60
    const int uv   = blockIdx.y;             // 0..24
    const int u    = uv / 5, v = uv % 5;
    const int b    = blockIdx.z;             // 0..7

    // one-time zero (halo + channel-invariant OOB chunks)
    float4* z = (float4*)sm;
    #pragma unroll
    for (int i = tid; i < SMEM_FLOATS / 4; i += 128)
        z[i] = make_float4(0.f, 0.f, 0.f, 0.f);
    __syncthreads();

    // ---- packed channel-invariant per-lane chunk indices ----
    uint32_t pk[5];
    #pragma unroll
    for (int i = 0; i < 5; i++) pk[i] = 0xFFFFFFFFu;

    const int kbase = (br == 1) ? 288 : 0;
    if (br < 2) {
        // union: 540 chunks = 9pl x 6r x 10ch; warp0 k<288, warp1 288..539
        #pragma unroll
        for (int i = 0; i < 9; i++) {
            int k = kbase + wl + 32 * i;
            uint32_t val = 0xFFFFu;
            if (k < 540) {
                int row = k / 10, ch = k - row * 10;
                int ab = row / 6, r = row - ab * 6;
                int gu = u + ab / 3 - 1, gv = v + ab % 3 - 1;
                int gh = th + r - 1,     gw = tw - 4 + ch * 4;
                if ((unsigned)gu < 5u && (unsigned)gv < 5u &&
                    (unsigned)gh < 64u && (unsigned)gw < 64u)
                    val = (uint32_t)((((gu * 5 + gv) * 64 + gh) * 64 + gw) >> 2);
            }
            int sh = 16 * (i & 1);
            pk[i >> 1] = (pk[i >> 1] & ~(0xFFFFu << sh)) | (val << sh);
        }
    } else {
        // uxy/vxy: 180 chunks = 3pl x 6r x 10ch
        #pragma unroll
        for (int i = 0; i < 6; i++) {
            int k = wl + 32 * i;
            uint32_t val = 0xFFFFu;
            if (k < 180) {
                int row = k / 10, ch = k - row * 10;
                int pkn = row / 6, r = row - pkn * 6;
                int gu = (br == 2) ? (u + pkn - 1) : u;
                int gv = (br == 2) ? v : (v + pkn - 1);
                int gh = th + r - 1, gw = tw - 4 + ch * 4;
                if ((unsigned)gu < 5u && (unsigned)gv < 5u &&
                    (unsigned)gh < 64u && (unsigned)gw < 64u)
                    val = (uint32_t)((((gu * 5 + gv) * 64 + gh) * 64 + gw) >> 2);
            }
            int sh = 16 * (i & 1);
            pk[i >> 1] = (pk[i >> 1] & ~(0xFFFFu << sh)) | (val << sh);
        }
    }

    const int xoff_f = (br < 2) ? 0 : (br == 2 ? UXY_F : VXY_F);
    uint32_t dstx[2], dstw[2];
    dstx[0] = sbase + xoff_f * 4 + (kbase + wl) * 16;
    dstx[1] = dstx[0] + STAGEB;
    dstw[0] = sbase + (WB_F + br * 216) * 4 + wl * 16;
    dstw[1] = dstw[0] + STAGEB;
    const float* sx_p[2] = { sm + xoff_f,          sm + STAGEF + xoff_f };
    const float* sw_p[2] = { sm + WB_F + br * 216, sm + STAGEF + WB_F + br * 216 };

    const char* xb = (const char*)x + (size_t)b * NC * CHB;
    const char* wb = (const char*)(g_wr + br * 216);

    u64 acc[4][4];
    #pragma unroll
    for (int p = 0; p < 4; p++)
        #pragma unroll
        for (int j = 0; j < 4; j++) acc[p][j] = 0ull;

    if (br < 2) {
        // ===== uv warps: shared union buffer, named barrier (id 1, 64 thr) =====
        stage_x<9>(pk, dstx[0], xb);
        stage_w(dstw[0], wb, wl);
        cp_commit();

        #pragma unroll 1
        for (int c = 0; c < NC; c++) {
            const int s = c & 1;
            if (c < NC - 1) {
                bar_sync(1, 64);   // peers done computing c-1 from buffer s^1
                stage_x<9>(pk, dstx[s ^ 1], xb + (size_t)(c + 1) * CHB);
                stage_w(dstw[s ^ 1], wb + (size_t)(c + 1) * 3456, wl);
                cp_commit();
                cp_wait1();        // own channel-c data complete
            } else {
                cp_wait0();
            }
            bar_sync(1, 64);       // peer's channel-c data complete + visible

            if (br == 0) comp_uvx(sx_p[s], sw_p[s], wl, acc);
            else         comp_uvy(sx_p[s], sw_p[s], wl, acc);
        }
    } else {
        // ===== hw warps: private buffers, wait_group pipeline =====
        stage_x<6>(pk, dstx[0], xb);
        stage_w(dstw[0], wb, wl);
        cp_commit();

        #pragma unroll 1
        for (int c = 0; c < NC; c++) {
            const int s = c & 1;
            if (c < NC - 1) {
                __syncwarp();
                stage_x<6>(pk, dstx[s ^ 1], xb + (size_t)(c + 1) * CHB);
                stage_w(dstw[s ^ 1], wb + (size_t)(c + 1) * 3456, wl);
                cp_commit();
                cp_wait1();
            } else {
                cp_wait0();
            }
            __syncwarp();
            comp_hw(sx_p[s], sw_p[s], wl, acc);
        }
    }

    // ---- epilogue: bias + PReLU + store ----
    const float slope = g_slope[br];
    const int ocb = br * 8;
    const size_t base0 = (size_t)b * 32 * CHSTRIDE + (size_t)ocb * CHSTRIDE +
                         (size_t)uv * (NH * NW) + (size_t)th * NW + (size_t)(tw + wl);
    #pragma unroll
    for (int j = 0; j < 4; j++) {
        const float b0 = g_bias[ocb + j * 2];
        const float b1 = g_bias[ocb + j * 2 + 1];
        const size_t cb0 = base0 + (size_t)(j * 2) * CHSTRIDE;
        const size_t cb1 = base0 + (size_t)(j * 2 + 1) * CHSTRIDE;
        #pragma unroll
        for (int p = 0; p < 4; p++) {
            float2 y = unpack2(acc[p][j]);
            float y0 = y.x + b0;
            float y1 = y.y + b1;
            y0 = (y0 >= 0.f) ? y0 : slope * y0;
            y1 = (y1 >= 0.f) ? y1 : slope * y1;
            out[cb0 + (size_t)p * NW] = y0;
            out[cb1 + (size_t)p * NW] = y1;
        }
    }
}

extern "C" void kernel_launch(void* const* d_in, const int* in_sizes, int n_in,
                              void* d_out, int out_size)
{
    const float* x = (const float*)d_in[0];

    prep_kernel<<<(NC * 864 + 255) / 256, 256>>>(
        (const float*)d_in[1], (const float*)d_in[4],
        (const float*)d_in[7], (const float*)d_in[10],
        (const float*)d_in[2], (const float*)d_in[5],
        (const float*)d_in[8], (const float*)d_in[11],
        (const float*)d_in[3], (const float*)d_in[6],
        (const float*)d_in[9], (const float*)d_in[12]);

    dim3 grid(32, 25, 8);   // (hw tiles: 2w x 16h, uv, batch)
    fe_kernel<<<grid, 128>>>(x, (float*)d_out);
}